// round 14
// baseline (speedup 1.0000x reference)
#include <cuda_runtime.h>
#include <cuda_bf16.h>
#include <cstddef>
#include <cstdint>

// Problem constants
#define NN_ 4096
#define FRAW 512
#define INF 1024
#define OUTF 4096

// ---------------------------------------------------------------------------
// Scratch (device globals — no allocation allowed)
// ---------------------------------------------------------------------------
__device__ __nv_bfloat16 g_Wth [(size_t)OUTF * INF];    // 8 MB   W^T hi
__device__ __nv_bfloat16 g_Wtl [(size_t)OUTF * INF];    // 8 MB   W^T lo
__device__ __nv_bfloat16 g_lwTh[(size_t)FRAW * INF];    // 1 MB   lw^T hi
__device__ __nv_bfloat16 g_lwTl[(size_t)FRAW * INF];    // 1 MB   lw^T lo
__device__ __nv_bfloat16 g_NFh [(size_t)NN_ * FRAW];    // 4 MB   NF hi
__device__ __nv_bfloat16 g_NFl [(size_t)NN_ * FRAW];    // 4 MB   NF lo
__device__ __nv_bfloat16 g_C1th[(size_t)OUTF * FRAW];   // 4 MB   (lw^T W)^T hi
__device__ __nv_bfloat16 g_C1tl[(size_t)OUTF * FRAW];   // 4 MB   (lw^T W)^T lo
__device__ float         g_c2  [OUTF];                  //        b @ W
__device__ int8_t        g_At8 [(size_t)NN_ * NN_];     // 16 MB  A^T int8
__device__ float         g_wf  [(size_t)NN_ * OUTF];    // 64 MB  wf fp32
__device__ __nv_bfloat16 g_wfTh[(size_t)OUTF * NN_];    // 32 MB  wf^T hi
__device__ __nv_bfloat16 g_wfTl[(size_t)OUTF * NN_];    // 32 MB  wf^T lo
__device__ __nv_bfloat16 g_Q   [(size_t)NN_ * NN_];     // 32 MB  Q = G.*S = P^T
__device__ __nv_bfloat16 g_Prm [(size_t)NN_ * NN_];     // 32 MB  P row-major
__device__ float         g_PW  [(size_t)NN_ * OUTF];    // 64 MB  P@wf fp32

// ---------------------------------------------------------------------------
// mma.sync / ldmatrix / cp.async helpers (sm_80+ — valid for compute_103 PTX)
// ---------------------------------------------------------------------------
__device__ __forceinline__ uint32_t smem_u32(const void* p) {
    uint32_t a;
    asm("{ .reg .u64 t; cvta.to.shared.u64 t, %1; cvt.u32.u64 %0, t; }" : "=r"(a) : "l"(p));
    return a;
}

#define LDMX4(rr, addr) \
    asm volatile("ldmatrix.sync.aligned.m8n8.x4.shared.b16 {%0,%1,%2,%3}, [%4];" \
        : "=r"((rr)[0]), "=r"((rr)[1]), "=r"((rr)[2]), "=r"((rr)[3]) : "r"(addr))

#define MMA16816(c, a, b0, b1) \
    asm volatile("mma.sync.aligned.m16n8k16.row.col.f32.bf16.bf16.f32 " \
        "{%0,%1,%2,%3}, {%4,%5,%6,%7}, {%8,%9}, {%0,%1,%2,%3};" \
        : "+f"((c)[0]), "+f"((c)[1]), "+f"((c)[2]), "+f"((c)[3]) \
        : "r"((a)[0]), "r"((a)[1]), "r"((a)[2]), "r"((a)[3]), "r"(b0), "r"(b1))

#define MMAS8(c, a, b0, b1) \
    asm volatile("mma.sync.aligned.m16n8k32.row.col.s32.s8.s8.s32 " \
        "{%0,%1,%2,%3}, {%4,%5,%6,%7}, {%8,%9}, {%0,%1,%2,%3};" \
        : "+r"((c)[0]), "+r"((c)[1]), "+r"((c)[2]), "+r"((c)[3]) \
        : "r"((a)[0]), "r"((a)[1]), "r"((a)[2]), "r"((a)[3]), "r"(b0), "r"(b1))

__device__ __forceinline__ void cp16(uint32_t d, const void* g) {
    asm volatile("cp.async.cg.shared.global [%0], [%1], 16;"
        :: "r"(d), "l"(__cvta_generic_to_global(g)));
}
#define CP_COMMIT() asm volatile("cp.async.commit_group;")
#define CP_WAIT2()  asm volatile("cp.async.wait_group 2;")

#define STAGES 4
#define STAGE_B 10240                      // per operand per stage
#define DSM_BYTES (2 * STAGES * STAGE_B)   // 81920 B dynamic smem

// ---------------------------------------------------------------------------
// bf16 tensor GEMM: C[128x128 tile] = sum over up to 3 phases of Ap @ Bp^T
//   Ap row-major [M, kcP*64] bf16; Bp row-major [N, kcP*64] bf16 (NT form)
//   EPI 1: outF[o] = v               EPI 2: outH=hi(v), outL=lo(v)
//   EPI 3: outF[o] = v + bias[col]
// 256 thr = 8 warps (2x4), warp tile 64x32, K-tile 32, 4-stage cp.async ring.
// ---------------------------------------------------------------------------
#define LDA 40    // padded row (bf16) = 80 B

template<int EPI>
__global__ __launch_bounds__(256, 1)
void tensor_gemm(const __nv_bfloat16* __restrict__ A0, const __nv_bfloat16* __restrict__ B0, int kc0,
                 const __nv_bfloat16* __restrict__ A1, const __nv_bfloat16* __restrict__ B1, int kc1,
                 const __nv_bfloat16* __restrict__ A2, const __nv_bfloat16* __restrict__ B2, int kc2,
                 float* __restrict__ outF, __nv_bfloat16* __restrict__ outH,
                 __nv_bfloat16* __restrict__ outL, const float* __restrict__ bias, int ldc)
{
    extern __shared__ char dsm[];
    const uint32_t sA = smem_u32(dsm);
    const uint32_t sB = sA + STAGES * STAGE_B;

    const int tid = threadIdx.x;
    const int lid = tid & 31, wid = tid >> 5;
    const int wm = wid >> 2, wn = wid & 3;
    const int m0 = blockIdx.y * 128, n0 = blockIdx.x * 128;
    const int r = tid >> 1, h = tid & 1;

    const int lr = lid & 7, grp = lid >> 3;
    const int a_ro = (grp & 1) * 8 + lr, a_co = (grp >> 1) * 8;
    const int b_ro = (grp >> 1) * 8 + lr, b_co = (grp & 1) * 8;

    float acc[4][4][4];
#pragma unroll
    for (int i = 0; i < 4; i++)
#pragma unroll
        for (int j = 0; j < 4; j++)
#pragma unroll
            for (int q = 0; q < 4; q++) acc[i][j][q] = 0.0f;

    const int T2 = 2 * (kc0 + kc1 + kc2);

    auto issue = [&](int t) {
        if (t < T2) {
            const __nv_bfloat16 *Ap, *Bp; size_t stride; int tl;
            if (t < 2 * kc0)              { Ap = A0; Bp = B0; stride = (size_t)kc0 * 64; tl = t; }
            else if (t < 2 * (kc0 + kc1)) { Ap = A1; Bp = B1; stride = (size_t)kc1 * 64; tl = t - 2 * kc0; }
            else                          { Ap = A2; Bp = B2; stride = (size_t)kc2 * 64; tl = t - 2 * (kc0 + kc1); }
            const int st = t & (STAGES - 1);
            const size_t koff = (size_t)tl * 32 + (size_t)h * 16;
            const __nv_bfloat16* ga = Ap + (size_t)(m0 + r) * stride + koff;
            const __nv_bfloat16* gb = Bp + (size_t)(n0 + r) * stride + koff;
            const uint32_t da = sA + st * STAGE_B + (uint32_t)(r * LDA + h * 16) * 2;
            const uint32_t db = sB + st * STAGE_B + (uint32_t)(r * LDA + h * 16) * 2;
            cp16(da, ga); cp16(da + 16, ga + 8);
            cp16(db, gb); cp16(db + 16, gb + 8);
        }
        CP_COMMIT();
    };

    issue(0); issue(1); issue(2);

    for (int kt = 0; kt < T2; kt++) {
        CP_WAIT2();
        __syncthreads();
        issue(kt + 3);

        const int st = kt & (STAGES - 1);
        const uint32_t baseA = sA + (uint32_t)st * STAGE_B;
        const uint32_t baseB = sB + (uint32_t)st * STAGE_B;
#pragma unroll
        for (int kk = 0; kk < 2; kk++) {
            uint32_t af[4][4], bf_[2][4];
#pragma unroll
            for (int mt = 0; mt < 4; mt++) {
                const uint32_t ad = baseA +
                    (uint32_t)((wm * 64 + mt * 16 + a_ro) * LDA + kk * 16 + a_co) * 2;
                LDMX4(af[mt], ad);
            }
#pragma unroll
            for (int nt = 0; nt < 2; nt++) {
                const uint32_t bd = baseB +
                    (uint32_t)((wn * 32 + nt * 16 + b_ro) * LDA + kk * 16 + b_co) * 2;
                LDMX4(bf_[nt], bd);
            }
#pragma unroll
            for (int mt = 0; mt < 4; mt++)
#pragma unroll
                for (int nb = 0; nb < 4; nb++)
                    MMA16816(acc[mt][nb], af[mt],
                             bf_[nb >> 1][(nb & 1) * 2], bf_[nb >> 1][(nb & 1) * 2 + 1]);
        }
    }

    const int er = lid >> 2, ec = (lid & 3) * 2;
#pragma unroll
    for (int mt = 0; mt < 4; mt++) {
#pragma unroll
        for (int nb = 0; nb < 4; nb++) {
            const int row = m0 + wm * 64 + mt * 16 + er;
            const int col = n0 + wn * 32 + nb * 8 + ec;
#pragma unroll
            for (int half = 0; half < 2; half++) {
                const size_t o = (size_t)(row + half * 8) * ldc + col;
                float v0 = acc[mt][nb][half * 2 + 0];
                float v1 = acc[mt][nb][half * 2 + 1];
                if (EPI == 1) {
                    float2 fv; fv.x = v0; fv.y = v1;
                    *(float2*)&outF[o] = fv;
                } else if (EPI == 2) {
                    const __nv_bfloat16 h0 = __float2bfloat16(v0);
                    const __nv_bfloat16 h1 = __float2bfloat16(v1);
                    __nv_bfloat162 hv; hv.x = h0; hv.y = h1;
                    *(__nv_bfloat162*)&outH[o] = hv;
                    __nv_bfloat162 lv;
                    lv.x = __float2bfloat16(v0 - __bfloat162float(h0));
                    lv.y = __float2bfloat16(v1 - __bfloat162float(h1));
                    *(__nv_bfloat162*)&outL[o] = lv;
                } else {  // EPI == 3
                    float2 fv; fv.x = v0 + bias[col]; fv.y = v1 + bias[col + 1];
                    *(float2*)&outF[o] = fv;
                }
            }
        }
    }
}

// ---------------------------------------------------------------------------
// int8 tensor GEMM (GEMM-3): Q[i][j] = bf16( (A8 @ A8^T)[i][j] * Smask[i][j] )
//   A8 row-major [4096, 4096] s8 (both operands). m16n8k32 s8 MMA, s32 accum.
//   K-tile = 64 bytes, row pad LDA8=80 B (16B-aligned rows, conflict-free).
// ---------------------------------------------------------------------------
#define LDA8 80

__global__ __launch_bounds__(256, 1)
void tensor_gemm_s8(const int8_t* __restrict__ A8, const float* __restrict__ Smask,
                    __nv_bfloat16* __restrict__ outH)
{
    extern __shared__ char dsm[];
    const uint32_t sA = smem_u32(dsm);
    const uint32_t sB = sA + STAGES * STAGE_B;

    const int tid = threadIdx.x;
    const int lid = tid & 31, wid = tid >> 5;
    const int wm = wid >> 2, wn = wid & 3;
    const int m0 = blockIdx.y * 128, n0 = blockIdx.x * 128;
    const int r = tid >> 1, h = tid & 1;

    const int lr = lid & 7, grp = lid >> 3;
    const int a_ro = (grp & 1) * 8 + lr, a_cb = (grp >> 1) * 16;   // byte cols
    const int b_ro = (grp >> 1) * 8 + lr, b_cb = (grp & 1) * 16;

    int acc[4][4][4];
#pragma unroll
    for (int i = 0; i < 4; i++)
#pragma unroll
        for (int j = 0; j < 4; j++)
#pragma unroll
            for (int q = 0; q < 4; q++) acc[i][j][q] = 0;

    const int T = NN_ / 64;   // 64 K-tiles of 64 bytes

    auto issue = [&](int t) {
        if (t < T) {
            const int st = t & (STAGES - 1);
            const size_t koff = (size_t)t * 64 + (size_t)h * 32;
            const int8_t* ga = A8 + (size_t)(m0 + r) * NN_ + koff;
            const int8_t* gb = A8 + (size_t)(n0 + r) * NN_ + koff;
            const uint32_t da = sA + st * STAGE_B + (uint32_t)(r * LDA8 + h * 32);
            const uint32_t db = sB + st * STAGE_B + (uint32_t)(r * LDA8 + h * 32);
            cp16(da, ga); cp16(da + 16, ga + 16);
            cp16(db, gb); cp16(db + 16, gb + 16);
        }
        CP_COMMIT();
    };

    issue(0); issue(1); issue(2);

    for (int kt = 0; kt < T; kt++) {
        CP_WAIT2();
        __syncthreads();
        issue(kt + 3);

        const int st = kt & (STAGES - 1);
        const uint32_t baseA = sA + (uint32_t)st * STAGE_B;
        const uint32_t baseB = sB + (uint32_t)st * STAGE_B;
#pragma unroll
        for (int kk = 0; kk < 2; kk++) {       // two k32 halves of the 64B tile
            uint32_t af[4][4], bf_[2][4];
#pragma unroll
            for (int mt = 0; mt < 4; mt++) {
                const uint32_t ad = baseA +
                    (uint32_t)((wm * 64 + mt * 16 + a_ro) * LDA8 + kk * 32 + a_cb);
                LDMX4(af[mt], ad);
            }
#pragma unroll
            for (int nt = 0; nt < 2; nt++) {
                const uint32_t bd = baseB +
                    (uint32_t)((wn * 32 + nt * 16 + b_ro) * LDA8 + kk * 32 + b_cb);
                LDMX4(bf_[nt], bd);
            }
#pragma unroll
            for (int mt = 0; mt < 4; mt++)
#pragma unroll
                for (int nb = 0; nb < 4; nb++)
                    MMAS8(acc[mt][nb], af[mt],
                          bf_[nb >> 1][(nb & 1) * 2], bf_[nb >> 1][(nb & 1) * 2 + 1]);
        }
    }

    const int er = lid >> 2, ec = (lid & 3) * 2;
#pragma unroll
    for (int mt = 0; mt < 4; mt++) {
#pragma unroll
        for (int nb = 0; nb < 4; nb++) {
            const int row = m0 + wm * 64 + mt * 16 + er;
            const int col = n0 + wn * 32 + nb * 8 + ec;
#pragma unroll
            for (int half = 0; half < 2; half++) {
                const size_t o = (size_t)(row + half * 8) * NN_ + col;
                const float v0 = (float)acc[mt][nb][half * 2 + 0] * Smask[o];
                const float v1 = (float)acc[mt][nb][half * 2 + 1] * Smask[o + 1];
                __nv_bfloat162 hv;
                hv.x = __float2bfloat16(v0); hv.y = __float2bfloat16(v1);
                *(__nv_bfloat162*)&outH[o] = hv;
            }
        }
    }
}

// ---------------------------------------------------------------------------
// Helper passes
// ---------------------------------------------------------------------------
template<bool SPLIT>
__global__ __launch_bounds__(256)
void transpose_cvt(const float* __restrict__ in, __nv_bfloat16* __restrict__ oh,
                   __nv_bfloat16* __restrict__ ol, int R, int C)
{
    __shared__ float t[32][33];
    const int rb = blockIdx.y * 32, cb = blockIdx.x * 32;
    const int tx = threadIdx.x, ty = threadIdx.y;
#pragma unroll
    for (int rr = 0; rr < 32; rr += 8)
        t[ty + rr][tx] = in[(size_t)(rb + ty + rr) * C + (cb + tx)];
    __syncthreads();
#pragma unroll
    for (int rr = 0; rr < 32; rr += 8) {
        const float v = t[tx][ty + rr];
        const size_t o = (size_t)(cb + ty + rr) * R + (rb + tx);
        const __nv_bfloat16 hh = __float2bfloat16(v);
        oh[o] = hh;
        if (SPLIT) ol[o] = __float2bfloat16(v - __bfloat162float(hh));
    }
}

__global__ __launch_bounds__(256)
void transpose_s8(const float* __restrict__ in, int8_t* __restrict__ out, int R, int C)
{
    __shared__ float t[32][33];
    const int rb = blockIdx.y * 32, cb = blockIdx.x * 32;
    const int tx = threadIdx.x, ty = threadIdx.y;
#pragma unroll
    for (int rr = 0; rr < 32; rr += 8)
        t[ty + rr][tx] = in[(size_t)(rb + ty + rr) * C + (cb + tx)];
    __syncthreads();
#pragma unroll
    for (int rr = 0; rr < 32; rr += 8)
        out[(size_t)(cb + ty + rr) * R + (rb + tx)] = (int8_t)t[tx][ty + rr];
}

__global__ __launch_bounds__(256)
void transpose_bf16(const __nv_bfloat16* __restrict__ in, __nv_bfloat16* __restrict__ out, int R, int C)
{
    __shared__ __nv_bfloat16 t[32][33];
    const int rb = blockIdx.y * 32, cb = blockIdx.x * 32;
    const int tx = threadIdx.x, ty = threadIdx.y;
#pragma unroll
    for (int rr = 0; rr < 32; rr += 8)
        t[ty + rr][tx] = in[(size_t)(rb + ty + rr) * C + (cb + tx)];
    __syncthreads();
#pragma unroll
    for (int rr = 0; rr < 32; rr += 8)
        out[(size_t)(cb + ty + rr) * R + (rb + tx)] = t[tx][ty + rr];
}

__global__ __launch_bounds__(256)
void split_cvt(const float* __restrict__ in, __nv_bfloat16* __restrict__ oh,
               __nv_bfloat16* __restrict__ ol, size_t n)
{
    const size_t i = (size_t)blockIdx.x * 256 + threadIdx.x;
    if (i < n) {
        const float v = in[i];
        const __nv_bfloat16 hh = __float2bfloat16(v);
        oh[i] = hh;
        ol[i] = __float2bfloat16(v - __bfloat162float(hh));
    }
}

// c2[n] = sum_i lb[i] * W[i][n]
__global__ __launch_bounds__(256)
void bias_w_kernel(const float* __restrict__ lb, const float* __restrict__ w,
                   float* __restrict__ c2)
{
    const int n = blockIdx.x * 256 + threadIdx.x;
    float s = 0.0f;
    for (int i = 0; i < INF; i++) s = fmaf(lb[i], w[(size_t)i * OUTF + n], s);
    c2[n] = s;
}

// out[k][j] = wf[j][k] * PW[j][k] / nc[k]^2
__global__ __launch_bounds__(256)
void finalize_kernel(const float* __restrict__ wf, const float* __restrict__ PW,
                     const float* __restrict__ nc, float* __restrict__ out)
{
    __shared__ float t[32][33];
    const int kb = blockIdx.x * 32;
    const int jb = blockIdx.y * 32;
    const int tx = threadIdx.x, ty = threadIdx.y;
#pragma unroll
    for (int rr = 0; rr < 32; rr += 8) {
        const size_t idx = (size_t)(jb + ty + rr) * NN_ + (kb + tx);
        t[ty + rr][tx] = wf[idx] * PW[idx];
    }
    __syncthreads();
#pragma unroll
    for (int rr = 0; rr < 32; rr += 8) {
        const int k = kb + ty + rr;
        const float n = nc[k];
        const float inv = 1.0f / (n * n);
        out[(size_t)k * NN_ + (jb + tx)] = t[tx][ty + rr] * inv;
    }
}

// ---------------------------------------------------------------------------
extern "C" void kernel_launch(void* const* d_in, const int* in_sizes, int n_in,
                              void* d_out, int out_size)
{
    const float* nf  = (const float*)d_in[0];  // (4096, 512)
    const float* adj = (const float*)d_in[1];  // (4096, 4096)
    const float* nc  = (const float*)d_in[3];  // (4096, 1)
    const float* S   = (const float*)d_in[4];  // mask_hadamard == S (4096, 4096)
    const float* lw  = (const float*)d_in[5];  // (1024, 512)
    const float* lb  = (const float*)d_in[6];  // (1024,)
    const float* w   = (const float*)d_in[7];  // (1024, 4096)
    float* out = (float*)d_out;

    float *wf, *PW, *c2;
    int8_t* At8;
    __nv_bfloat16 *Wth, *Wtl, *lwTh, *lwTl, *NFh, *NFl, *C1th, *C1tl, *wfTh, *wfTl, *Q, *Prm;
    cudaGetSymbolAddress((void**)&Wth,  g_Wth);
    cudaGetSymbolAddress((void**)&Wtl,  g_Wtl);
    cudaGetSymbolAddress((void**)&lwTh, g_lwTh);
    cudaGetSymbolAddress((void**)&lwTl, g_lwTl);
    cudaGetSymbolAddress((void**)&NFh,  g_NFh);
    cudaGetSymbolAddress((void**)&NFl,  g_NFl);
    cudaGetSymbolAddress((void**)&C1th, g_C1th);
    cudaGetSymbolAddress((void**)&C1tl, g_C1tl);
    cudaGetSymbolAddress((void**)&c2,   g_c2);
    cudaGetSymbolAddress((void**)&At8,  g_At8);
    cudaGetSymbolAddress((void**)&wf,   g_wf);
    cudaGetSymbolAddress((void**)&wfTh, g_wfTh);
    cudaGetSymbolAddress((void**)&wfTl, g_wfTl);
    cudaGetSymbolAddress((void**)&Q,    g_Q);
    cudaGetSymbolAddress((void**)&Prm,  g_Prm);
    cudaGetSymbolAddress((void**)&PW,   g_PW);

    cudaFuncSetAttribute(tensor_gemm<1>, cudaFuncAttributeMaxDynamicSharedMemorySize, DSM_BYTES);
    cudaFuncSetAttribute(tensor_gemm<2>, cudaFuncAttributeMaxDynamicSharedMemorySize, DSM_BYTES);
    cudaFuncSetAttribute(tensor_gemm<3>, cudaFuncAttributeMaxDynamicSharedMemorySize, DSM_BYTES);
    cudaFuncSetAttribute(tensor_gemm_s8, cudaFuncAttributeMaxDynamicSharedMemorySize, DSM_BYTES);

    // --- operand prep ---
    transpose_cvt<true><<<dim3(OUTF/32, INF/32), dim3(32, 8)>>>(w, Wth, Wtl, INF, OUTF);
    transpose_cvt<true><<<dim3(FRAW/32, INF/32), dim3(32, 8)>>>(lw, lwTh, lwTl, INF, FRAW);
    split_cvt<<<(unsigned)(((size_t)NN_*FRAW + 255)/256), 256>>>(nf, NFh, NFl, (size_t)NN_*FRAW);
    transpose_s8<<<dim3(NN_/32, NN_/32), dim3(32, 8)>>>(adj, At8, NN_, NN_);
    bias_w_kernel<<<OUTF/256, 256>>>(lb, w, c2);

    // --- C1^T = W^T @ lw  (4096 x 512), written as bf16 hi/lo ---
    tensor_gemm<2><<<dim3(FRAW/128, OUTF/128), 256, DSM_BYTES>>>(
        Wth, lwTh, INF/64,  Wth, lwTl, INF/64,  Wtl, lwTh, INF/64,
        nullptr, C1th, C1tl, nullptr, FRAW);

    // --- wf = NF @ C1 + c2   (K = 512, 3-term split, fp32 out + bias) ---
    tensor_gemm<3><<<dim3(OUTF/128, NN_/128), 256, DSM_BYTES>>>(
        NFh, C1th, FRAW/64,  NFh, C1tl, FRAW/64,  NFl, C1th, FRAW/64,
        wf, nullptr, nullptr, c2, OUTF);

    // --- wf^T hi/lo split for GEMM-4's B operand ---
    transpose_cvt<true><<<dim3(OUTF/32, NN_/32), dim3(32, 8)>>>(wf, wfTh, wfTl, NN_, OUTF);

    // --- GEMM-3 (int8, exact): Q = (A^T A) .* S  (aligned; Q = P^T by symmetry) ---
    tensor_gemm_s8<<<dim3(NN_/128, NN_/128), 256, DSM_BYTES>>>(At8, S, Q);

    // --- P row-major = Q^T ---
    transpose_bf16<<<dim3(NN_/32, NN_/32), dim3(32, 8)>>>(Q, Prm, NN_, NN_);

    // --- GEMM-4 (bf16, wf split): PW = P@wfh + P@wfl ---
    tensor_gemm<1><<<dim3(OUTF/128, NN_/128), 256, DSM_BYTES>>>(
        Prm, wfTh, NN_/64,  Prm, wfTl, NN_/64,  nullptr, nullptr, 0,
        PW, nullptr, nullptr, nullptr, OUTF);

    // --- out[k][j] = wf[j][k]*PW[j][k]/nc[k]^2 ---
    finalize_kernel<<<dim3(NN_/32, NN_/32), dim3(32, 8)>>>(wf, PW, nc, out);
}

// round 15
// speedup vs baseline: 1.8372x; 1.8372x over previous
#include <cuda_runtime.h>
#include <cuda_bf16.h>
#include <cstddef>
#include <cstdint>

// Problem constants
#define NN_ 4096
#define FRAW 512
#define INF 1024
#define OUTF 4096

// ---------------------------------------------------------------------------
// Scratch (device globals — no allocation allowed)
// ---------------------------------------------------------------------------
__device__ __nv_bfloat16 g_Wth [(size_t)OUTF * INF];    // 8 MB   W^T hi
__device__ __nv_bfloat16 g_Wtl [(size_t)OUTF * INF];    // 8 MB   W^T lo
__device__ __nv_bfloat16 g_lwTh[(size_t)FRAW * INF];    // 1 MB   lw^T hi
__device__ __nv_bfloat16 g_lwTl[(size_t)FRAW * INF];    // 1 MB   lw^T lo
__device__ __nv_bfloat16 g_NFh [(size_t)NN_ * FRAW];    // 4 MB   NF hi
__device__ __nv_bfloat16 g_NFl [(size_t)NN_ * FRAW];    // 4 MB   NF lo
__device__ __nv_bfloat16 g_C1th[(size_t)OUTF * FRAW];   // 4 MB   (lw^T W)^T hi
__device__ __nv_bfloat16 g_C1tl[(size_t)OUTF * FRAW];   // 4 MB   (lw^T W)^T lo
__device__ float         g_c2  [OUTF];                  //        b @ W
__device__ __nv_bfloat16 g_At  [(size_t)NN_ * NN_];     // 32 MB  A^T bf16
__device__ float         g_wf  [(size_t)NN_ * OUTF];    // 64 MB  wf fp32
__device__ __nv_bfloat16 g_wfTh[(size_t)OUTF * NN_];    // 32 MB  wf^T hi
__device__ __nv_bfloat16 g_wfTl[(size_t)OUTF * NN_];    // 32 MB  wf^T lo
__device__ __nv_bfloat16 g_Q   [(size_t)NN_ * NN_];     // 32 MB  Q = G.*S = P^T
__device__ __nv_bfloat16 g_Prm [(size_t)NN_ * NN_];     // 32 MB  P row-major
__device__ float         g_PW  [(size_t)NN_ * OUTF];    // 64 MB  P@wf fp32

// ---------------------------------------------------------------------------
// mma.sync / ldmatrix / cp.async helpers (sm_80+ — valid for compute_103 PTX)
// ---------------------------------------------------------------------------
__device__ __forceinline__ uint32_t smem_u32(const void* p) {
    uint32_t a;
    asm("{ .reg .u64 t; cvta.to.shared.u64 t, %1; cvt.u32.u64 %0, t; }" : "=r"(a) : "l"(p));
    return a;
}

#define LDMX4(rr, addr) \
    asm volatile("ldmatrix.sync.aligned.m8n8.x4.shared.b16 {%0,%1,%2,%3}, [%4];" \
        : "=r"((rr)[0]), "=r"((rr)[1]), "=r"((rr)[2]), "=r"((rr)[3]) : "r"(addr))

#define MMA16816(c, a, b0, b1) \
    asm volatile("mma.sync.aligned.m16n8k16.row.col.f32.bf16.bf16.f32 " \
        "{%0,%1,%2,%3}, {%4,%5,%6,%7}, {%8,%9}, {%0,%1,%2,%3};" \
        : "+f"((c)[0]), "+f"((c)[1]), "+f"((c)[2]), "+f"((c)[3]) \
        : "r"((a)[0]), "r"((a)[1]), "r"((a)[2]), "r"((a)[3]), "r"(b0), "r"(b1))

__device__ __forceinline__ void cp16(uint32_t d, const void* g) {
    asm volatile("cp.async.cg.shared.global [%0], [%1], 16;"
        :: "r"(d), "l"(__cvta_generic_to_global(g)));
}
#define CP_COMMIT() asm volatile("cp.async.commit_group;")
#define CP_WAIT2()  asm volatile("cp.async.wait_group 2;")

#define STAGES 4
#define STAGE_B 10240                      // per operand per stage
#define DSM_BYTES (2 * STAGES * STAGE_B)   // 81920 B dynamic smem

// ---------------------------------------------------------------------------
// bf16 tensor GEMM: C[128x128 tile] = sum over up to 3 phases of Ap @ Bp^T
//   Ap row-major [M, kcP*64] bf16; Bp row-major [N, kcP*64] bf16 (NT form)
//   EPI 0: outH[o] = bf16(v * Smask[o])    (GEMM-3: Q = G.*S)
//   EPI 1: outF[o] = v                     (GEMM-4)
//   EPI 2: outH = hi(v), outL = lo(v)      (C1 split)
//   EPI 3: outF[o] = v + bias[col]         (wf + c2)
// 256 thr = 8 warps (2x4), warp tile 64x32, K-tile 32, 4-stage cp.async ring.
// ---------------------------------------------------------------------------
#define LDA 40    // padded row (bf16) = 80 B

template<int EPI>
__global__ __launch_bounds__(256, 1)
void tensor_gemm(const __nv_bfloat16* __restrict__ A0, const __nv_bfloat16* __restrict__ B0, int kc0,
                 const __nv_bfloat16* __restrict__ A1, const __nv_bfloat16* __restrict__ B1, int kc1,
                 const __nv_bfloat16* __restrict__ A2, const __nv_bfloat16* __restrict__ B2, int kc2,
                 float* __restrict__ outF, __nv_bfloat16* __restrict__ outH,
                 __nv_bfloat16* __restrict__ outL, const float* __restrict__ bias,
                 const float* __restrict__ Smask, int ldc)
{
    extern __shared__ char dsm[];
    const uint32_t sA = smem_u32(dsm);
    const uint32_t sB = sA + STAGES * STAGE_B;

    const int tid = threadIdx.x;
    const int lid = tid & 31, wid = tid >> 5;
    const int wm = wid >> 2, wn = wid & 3;
    const int m0 = blockIdx.y * 128, n0 = blockIdx.x * 128;
    const int r = tid >> 1, h = tid & 1;

    const int lr = lid & 7, grp = lid >> 3;
    const int a_ro = (grp & 1) * 8 + lr, a_co = (grp >> 1) * 8;
    const int b_ro = (grp >> 1) * 8 + lr, b_co = (grp & 1) * 8;

    float acc[4][4][4];
#pragma unroll
    for (int i = 0; i < 4; i++)
#pragma unroll
        for (int j = 0; j < 4; j++)
#pragma unroll
            for (int q = 0; q < 4; q++) acc[i][j][q] = 0.0f;

    const int T2 = 2 * (kc0 + kc1 + kc2);

    auto issue = [&](int t) {
        if (t < T2) {
            const __nv_bfloat16 *Ap, *Bp; size_t stride; int tl;
            if (t < 2 * kc0)              { Ap = A0; Bp = B0; stride = (size_t)kc0 * 64; tl = t; }
            else if (t < 2 * (kc0 + kc1)) { Ap = A1; Bp = B1; stride = (size_t)kc1 * 64; tl = t - 2 * kc0; }
            else                          { Ap = A2; Bp = B2; stride = (size_t)kc2 * 64; tl = t - 2 * (kc0 + kc1); }
            const int st = t & (STAGES - 1);
            const size_t koff = (size_t)tl * 32 + (size_t)h * 16;
            const __nv_bfloat16* ga = Ap + (size_t)(m0 + r) * stride + koff;
            const __nv_bfloat16* gb = Bp + (size_t)(n0 + r) * stride + koff;
            const uint32_t da = sA + st * STAGE_B + (uint32_t)(r * LDA + h * 16) * 2;
            const uint32_t db = sB + st * STAGE_B + (uint32_t)(r * LDA + h * 16) * 2;
            cp16(da, ga); cp16(da + 16, ga + 8);
            cp16(db, gb); cp16(db + 16, gb + 8);
        }
        CP_COMMIT();
    };

    issue(0); issue(1); issue(2);

    for (int kt = 0; kt < T2; kt++) {
        CP_WAIT2();
        __syncthreads();
        issue(kt + 3);

        const int st = kt & (STAGES - 1);
        const uint32_t baseA = sA + (uint32_t)st * STAGE_B;
        const uint32_t baseB = sB + (uint32_t)st * STAGE_B;
#pragma unroll
        for (int kk = 0; kk < 2; kk++) {
            uint32_t af[4][4], bf_[2][4];
#pragma unroll
            for (int mt = 0; mt < 4; mt++) {
                const uint32_t ad = baseA +
                    (uint32_t)((wm * 64 + mt * 16 + a_ro) * LDA + kk * 16 + a_co) * 2;
                LDMX4(af[mt], ad);
            }
#pragma unroll
            for (int nt = 0; nt < 2; nt++) {
                const uint32_t bd = baseB +
                    (uint32_t)((wn * 32 + nt * 16 + b_ro) * LDA + kk * 16 + b_co) * 2;
                LDMX4(bf_[nt], bd);
            }
#pragma unroll
            for (int mt = 0; mt < 4; mt++)
#pragma unroll
                for (int nb = 0; nb < 4; nb++)
                    MMA16816(acc[mt][nb], af[mt],
                             bf_[nb >> 1][(nb & 1) * 2], bf_[nb >> 1][(nb & 1) * 2 + 1]);
        }
    }

    const int er = lid >> 2, ec = (lid & 3) * 2;
#pragma unroll
    for (int mt = 0; mt < 4; mt++) {
#pragma unroll
        for (int nb = 0; nb < 4; nb++) {
            const int row = m0 + wm * 64 + mt * 16 + er;
            const int col = n0 + wn * 32 + nb * 8 + ec;
#pragma unroll
            for (int half = 0; half < 2; half++) {
                const size_t o = (size_t)(row + half * 8) * ldc + col;
                float v0 = acc[mt][nb][half * 2 + 0];
                float v1 = acc[mt][nb][half * 2 + 1];
                if (EPI == 0) {
                    v0 *= Smask[o]; v1 *= Smask[o + 1];
                    __nv_bfloat162 hv;
                    hv.x = __float2bfloat16(v0); hv.y = __float2bfloat16(v1);
                    *(__nv_bfloat162*)&outH[o] = hv;
                } else if (EPI == 1) {
                    float2 fv; fv.x = v0; fv.y = v1;
                    *(float2*)&outF[o] = fv;
                } else if (EPI == 2) {
                    const __nv_bfloat16 h0 = __float2bfloat16(v0);
                    const __nv_bfloat16 h1 = __float2bfloat16(v1);
                    __nv_bfloat162 hv; hv.x = h0; hv.y = h1;
                    *(__nv_bfloat162*)&outH[o] = hv;
                    __nv_bfloat162 lv;
                    lv.x = __float2bfloat16(v0 - __bfloat162float(h0));
                    lv.y = __float2bfloat16(v1 - __bfloat162float(h1));
                    *(__nv_bfloat162*)&outL[o] = lv;
                } else {  // EPI == 3
                    float2 fv; fv.x = v0 + bias[col]; fv.y = v1 + bias[col + 1];
                    *(float2*)&outF[o] = fv;
                }
            }
        }
    }
}

// ---------------------------------------------------------------------------
// Helper passes
// ---------------------------------------------------------------------------
template<bool SPLIT>
__global__ __launch_bounds__(256)
void transpose_cvt(const float* __restrict__ in, __nv_bfloat16* __restrict__ oh,
                   __nv_bfloat16* __restrict__ ol, int R, int C)
{
    __shared__ float t[32][33];
    const int rb = blockIdx.y * 32, cb = blockIdx.x * 32;
    const int tx = threadIdx.x, ty = threadIdx.y;
#pragma unroll
    for (int rr = 0; rr < 32; rr += 8)
        t[ty + rr][tx] = in[(size_t)(rb + ty + rr) * C + (cb + tx)];
    __syncthreads();
#pragma unroll
    for (int rr = 0; rr < 32; rr += 8) {
        const float v = t[tx][ty + rr];
        const size_t o = (size_t)(cb + ty + rr) * R + (rb + tx);
        const __nv_bfloat16 hh = __float2bfloat16(v);
        oh[o] = hh;
        if (SPLIT) ol[o] = __float2bfloat16(v - __bfloat162float(hh));
    }
}

__global__ __launch_bounds__(256)
void transpose_bf16(const __nv_bfloat16* __restrict__ in, __nv_bfloat16* __restrict__ out, int R, int C)
{
    __shared__ __nv_bfloat16 t[32][33];
    const int rb = blockIdx.y * 32, cb = blockIdx.x * 32;
    const int tx = threadIdx.x, ty = threadIdx.y;
#pragma unroll
    for (int rr = 0; rr < 32; rr += 8)
        t[ty + rr][tx] = in[(size_t)(rb + ty + rr) * C + (cb + tx)];
    __syncthreads();
#pragma unroll
    for (int rr = 0; rr < 32; rr += 8)
        out[(size_t)(cb + ty + rr) * R + (rb + tx)] = t[tx][ty + rr];
}

__global__ __launch_bounds__(256)
void split_cvt(const float* __restrict__ in, __nv_bfloat16* __restrict__ oh,
               __nv_bfloat16* __restrict__ ol, size_t n)
{
    const size_t i = (size_t)blockIdx.x * 256 + threadIdx.x;
    if (i < n) {
        const float v = in[i];
        const __nv_bfloat16 hh = __float2bfloat16(v);
        oh[i] = hh;
        ol[i] = __float2bfloat16(v - __bfloat162float(hh));
    }
}

// c2[n] = sum_i lb[i] * W[i][n]
__global__ __launch_bounds__(256)
void bias_w_kernel(const float* __restrict__ lb, const float* __restrict__ w,
                   float* __restrict__ c2)
{
    const int n = blockIdx.x * 256 + threadIdx.x;
    float s = 0.0f;
#pragma unroll 8
    for (int i = 0; i < INF; i++) s = fmaf(lb[i], w[(size_t)i * OUTF + n], s);
    c2[n] = s;
}

// out[k][j] = wf[j][k] * PW[j][k] / nc[k]^2
__global__ __launch_bounds__(256)
void finalize_kernel(const float* __restrict__ wf, const float* __restrict__ PW,
                     const float* __restrict__ nc, float* __restrict__ out)
{
    __shared__ float t[32][33];
    const int kb = blockIdx.x * 32;
    const int jb = blockIdx.y * 32;
    const int tx = threadIdx.x, ty = threadIdx.y;
#pragma unroll
    for (int rr = 0; rr < 32; rr += 8) {
        const size_t idx = (size_t)(jb + ty + rr) * NN_ + (kb + tx);
        t[ty + rr][tx] = wf[idx] * PW[idx];
    }
    __syncthreads();
#pragma unroll
    for (int rr = 0; rr < 32; rr += 8) {
        const int k = kb + ty + rr;
        const float n = nc[k];
        const float inv = 1.0f / (n * n);
        out[(size_t)k * NN_ + (jb + tx)] = t[tx][ty + rr] * inv;
    }
}

// ---------------------------------------------------------------------------
extern "C" void kernel_launch(void* const* d_in, const int* in_sizes, int n_in,
                              void* d_out, int out_size)
{
    const float* nf  = (const float*)d_in[0];  // (4096, 512)
    const float* adj = (const float*)d_in[1];  // (4096, 4096)
    const float* nc  = (const float*)d_in[3];  // (4096, 1)
    const float* S   = (const float*)d_in[4];  // mask_hadamard == S (4096, 4096)
    const float* lw  = (const float*)d_in[5];  // (1024, 512)
    const float* lb  = (const float*)d_in[6];  // (1024,)
    const float* w   = (const float*)d_in[7];  // (1024, 4096)
    float* out = (float*)d_out;

    float *wf, *PW, *c2;
    __nv_bfloat16 *Wth, *Wtl, *lwTh, *lwTl, *NFh, *NFl, *C1th, *C1tl, *At, *wfTh, *wfTl, *Q, *Prm;
    cudaGetSymbolAddress((void**)&Wth,  g_Wth);
    cudaGetSymbolAddress((void**)&Wtl,  g_Wtl);
    cudaGetSymbolAddress((void**)&lwTh, g_lwTh);
    cudaGetSymbolAddress((void**)&lwTl, g_lwTl);
    cudaGetSymbolAddress((void**)&NFh,  g_NFh);
    cudaGetSymbolAddress((void**)&NFl,  g_NFl);
    cudaGetSymbolAddress((void**)&C1th, g_C1th);
    cudaGetSymbolAddress((void**)&C1tl, g_C1tl);
    cudaGetSymbolAddress((void**)&c2,   g_c2);
    cudaGetSymbolAddress((void**)&At,   g_At);
    cudaGetSymbolAddress((void**)&wf,   g_wf);
    cudaGetSymbolAddress((void**)&wfTh, g_wfTh);
    cudaGetSymbolAddress((void**)&wfTl, g_wfTl);
    cudaGetSymbolAddress((void**)&Q,    g_Q);
    cudaGetSymbolAddress((void**)&Prm,  g_Prm);
    cudaGetSymbolAddress((void**)&PW,   g_PW);

    cudaFuncSetAttribute(tensor_gemm<0>, cudaFuncAttributeMaxDynamicSharedMemorySize, DSM_BYTES);
    cudaFuncSetAttribute(tensor_gemm<1>, cudaFuncAttributeMaxDynamicSharedMemorySize, DSM_BYTES);
    cudaFuncSetAttribute(tensor_gemm<2>, cudaFuncAttributeMaxDynamicSharedMemorySize, DSM_BYTES);
    cudaFuncSetAttribute(tensor_gemm<3>, cudaFuncAttributeMaxDynamicSharedMemorySize, DSM_BYTES);

    // --- operand prep ---
    transpose_cvt<true ><<<dim3(OUTF/32, INF/32), dim3(32, 8)>>>(w, Wth, Wtl, INF, OUTF);
    transpose_cvt<true ><<<dim3(FRAW/32, INF/32), dim3(32, 8)>>>(lw, lwTh, lwTl, INF, FRAW);
    split_cvt<<<(unsigned)(((size_t)NN_*FRAW + 255)/256), 256>>>(nf, NFh, NFl, (size_t)NN_*FRAW);
    transpose_cvt<false><<<dim3(NN_/32, NN_/32), dim3(32, 8)>>>(adj, At, nullptr, NN_, NN_);
    bias_w_kernel<<<OUTF/256, 256>>>(lb, w, c2);

    // --- C1^T = W^T @ lw  (4096 x 512), 3-term split, bf16 hi/lo out ---
    tensor_gemm<2><<<dim3(FRAW/128, OUTF/128), 256, DSM_BYTES>>>(
        Wth, lwTh, INF/64,  Wth, lwTl, INF/64,  Wtl, lwTh, INF/64,
        nullptr, C1th, C1tl, nullptr, nullptr, FRAW);

    // --- wf = NF @ C1 + c2   (K = 512, 3-term split, fp32 out + bias) ---
    tensor_gemm<3><<<dim3(OUTF/128, NN_/128), 256, DSM_BYTES>>>(
        NFh, C1th, FRAW/64,  NFh, C1tl, FRAW/64,  NFl, C1th, FRAW/64,
        wf, nullptr, nullptr, c2, nullptr, OUTF);

    // --- wf^T hi/lo split for GEMM-4's B operand ---
    transpose_cvt<true><<<dim3(OUTF/32, NN_/32), dim3(32, 8)>>>(wf, wfTh, wfTl, NN_, OUTF);

    // --- GEMM-3 (bf16, exact): Q = (A^T A) .* S  (aligned mask; Q = P^T) ---
    tensor_gemm<0><<<dim3(NN_/128, NN_/128), 256, DSM_BYTES>>>(
        At, At, NN_/64,  nullptr, nullptr, 0,  nullptr, nullptr, 0,
        nullptr, Q, nullptr, nullptr, S, NN_);

    // --- P row-major = Q^T ---
    transpose_bf16<<<dim3(NN_/32, NN_/32), dim3(32, 8)>>>(Q, Prm, NN_, NN_);

    // --- GEMM-4 (bf16, wf split): PW = P@wfh + P@wfl ---
    tensor_gemm<1><<<dim3(OUTF/128, NN_/128), 256, DSM_BYTES>>>(
        Prm, wfTh, NN_/64,  Prm, wfTl, NN_/64,  nullptr, nullptr, 0,
        PW, nullptr, nullptr, nullptr, nullptr, OUTF);

    // --- out[k][j] = wf[j][k]*PW[j][k]/nc[k]^2 ---
    finalize_kernel<<<dim3(NN_/32, NN_/32), dim3(32, 8)>>>(wf, PW, nc, out);
}

// round 16
// speedup vs baseline: 2.0683x; 1.1258x over previous
#include <cuda_runtime.h>
#include <cuda_bf16.h>
#include <cstddef>
#include <cstdint>

// Problem constants
#define NN_ 4096
#define FRAW 512
#define INF 1024
#define OUTF 4096

// ---------------------------------------------------------------------------
// Scratch (device globals — no allocation allowed)
// ---------------------------------------------------------------------------
__device__ __nv_bfloat16 g_Wth [(size_t)OUTF * INF];    // 8 MB   W^T hi
__device__ __nv_bfloat16 g_Wtl [(size_t)OUTF * INF];    // 8 MB   W^T lo
__device__ __nv_bfloat16 g_lwTh[(size_t)FRAW * INF];    // 1 MB   lw^T hi
__device__ __nv_bfloat16 g_lwTl[(size_t)FRAW * INF];    // 1 MB   lw^T lo
__device__ __nv_bfloat16 g_NFh [(size_t)NN_ * FRAW];    // 4 MB   NF hi
__device__ __nv_bfloat16 g_NFl [(size_t)NN_ * FRAW];    // 4 MB   NF lo
__device__ __nv_bfloat16 g_C1th[(size_t)OUTF * FRAW];   // 4 MB   (lw^T W)^T hi
__device__ __nv_bfloat16 g_C1tl[(size_t)OUTF * FRAW];   // 4 MB   (lw^T W)^T lo
__device__ float         g_c2  [OUTF];                  //        b @ W
__device__ __nv_bfloat16 g_At  [(size_t)NN_ * NN_];     // 32 MB  A^T bf16
__device__ float         g_wf  [(size_t)NN_ * OUTF];    // 64 MB  wf fp32
__device__ __nv_bfloat16 g_wfTh[(size_t)OUTF * NN_];    // 32 MB  wf^T hi
__device__ __nv_bfloat16 g_wfTl[(size_t)OUTF * NN_];    // 32 MB  wf^T lo
__device__ __nv_bfloat16 g_Prm [(size_t)NN_ * NN_];     // 32 MB  P row-major
__device__ float         g_PW  [(size_t)NN_ * OUTF];    // 64 MB  P@wf fp32

// ---------------------------------------------------------------------------
// mma.sync / ldmatrix / cp.async helpers (sm_80+ — valid for compute_103 PTX)
// ---------------------------------------------------------------------------
__device__ __forceinline__ uint32_t smem_u32(const void* p) {
    uint32_t a;
    asm("{ .reg .u64 t; cvta.to.shared.u64 t, %1; cvt.u32.u64 %0, t; }" : "=r"(a) : "l"(p));
    return a;
}

#define LDMX4(rr, addr) \
    asm volatile("ldmatrix.sync.aligned.m8n8.x4.shared.b16 {%0,%1,%2,%3}, [%4];" \
        : "=r"((rr)[0]), "=r"((rr)[1]), "=r"((rr)[2]), "=r"((rr)[3]) : "r"(addr))

#define MMA16816(c, a, b0, b1) \
    asm volatile("mma.sync.aligned.m16n8k16.row.col.f32.bf16.bf16.f32 " \
        "{%0,%1,%2,%3}, {%4,%5,%6,%7}, {%8,%9}, {%0,%1,%2,%3};" \
        : "+f"((c)[0]), "+f"((c)[1]), "+f"((c)[2]), "+f"((c)[3]) \
        : "r"((a)[0]), "r"((a)[1]), "r"((a)[2]), "r"((a)[3]), "r"(b0), "r"(b1))

__device__ __forceinline__ void cp16(uint32_t d, const void* g) {
    asm volatile("cp.async.cg.shared.global [%0], [%1], 16;"
        :: "r"(d), "l"(__cvta_generic_to_global(g)));
}
#define CP_COMMIT() asm volatile("cp.async.commit_group;")
#define CP_WAIT2()  asm volatile("cp.async.wait_group 2;")

#define STAGES 4
#define STAGE_B 10240                      // per operand per stage
#define DSM_BYTES (2 * STAGES * STAGE_B)   // 81920 B dynamic smem

// ---------------------------------------------------------------------------
// bf16 tensor GEMM: C[128x128 tile] = sum over up to 3 phases of Ap @ Bp^T
//   EPI 1: outF[o] = v        EPI 2: outH=hi(v), outL=lo(v)
//   EPI 3: outF[o] = v + bias[col]
// 256 thr = 8 warps (2x4), warp tile 64x32, K-tile 32, 4-stage cp.async ring.
// ---------------------------------------------------------------------------
#define LDA 40    // padded row (bf16) = 80 B

template<int EPI>
__global__ __launch_bounds__(256, 1)
void tensor_gemm(const __nv_bfloat16* __restrict__ A0, const __nv_bfloat16* __restrict__ B0, int kc0,
                 const __nv_bfloat16* __restrict__ A1, const __nv_bfloat16* __restrict__ B1, int kc1,
                 const __nv_bfloat16* __restrict__ A2, const __nv_bfloat16* __restrict__ B2, int kc2,
                 float* __restrict__ outF, __nv_bfloat16* __restrict__ outH,
                 __nv_bfloat16* __restrict__ outL, const float* __restrict__ bias, int ldc)
{
    extern __shared__ char dsm[];
    const uint32_t sA = smem_u32(dsm);
    const uint32_t sB = sA + STAGES * STAGE_B;

    const int tid = threadIdx.x;
    const int lid = tid & 31, wid = tid >> 5;
    const int wm = wid >> 2, wn = wid & 3;
    const int m0 = blockIdx.y * 128, n0 = blockIdx.x * 128;
    const int r = tid >> 1, h = tid & 1;

    const int lr = lid & 7, grp = lid >> 3;
    const int a_ro = (grp & 1) * 8 + lr, a_co = (grp >> 1) * 8;
    const int b_ro = (grp >> 1) * 8 + lr, b_co = (grp & 1) * 8;

    float acc[4][4][4];
#pragma unroll
    for (int i = 0; i < 4; i++)
#pragma unroll
        for (int j = 0; j < 4; j++)
#pragma unroll
            for (int q = 0; q < 4; q++) acc[i][j][q] = 0.0f;

    const int T2 = 2 * (kc0 + kc1 + kc2);

    auto issue = [&](int t) {
        if (t < T2) {
            const __nv_bfloat16 *Ap, *Bp; size_t stride; int tl;
            if (t < 2 * kc0)              { Ap = A0; Bp = B0; stride = (size_t)kc0 * 64; tl = t; }
            else if (t < 2 * (kc0 + kc1)) { Ap = A1; Bp = B1; stride = (size_t)kc1 * 64; tl = t - 2 * kc0; }
            else                          { Ap = A2; Bp = B2; stride = (size_t)kc2 * 64; tl = t - 2 * (kc0 + kc1); }
            const int st = t & (STAGES - 1);
            const size_t koff = (size_t)tl * 32 + (size_t)h * 16;
            const __nv_bfloat16* ga = Ap + (size_t)(m0 + r) * stride + koff;
            const __nv_bfloat16* gb = Bp + (size_t)(n0 + r) * stride + koff;
            const uint32_t da = sA + st * STAGE_B + (uint32_t)(r * LDA + h * 16) * 2;
            const uint32_t db = sB + st * STAGE_B + (uint32_t)(r * LDA + h * 16) * 2;
            cp16(da, ga); cp16(da + 16, ga + 8);
            cp16(db, gb); cp16(db + 16, gb + 8);
        }
        CP_COMMIT();
    };

    issue(0); issue(1); issue(2);

    for (int kt = 0; kt < T2; kt++) {
        CP_WAIT2();
        __syncthreads();
        issue(kt + 3);

        const int st = kt & (STAGES - 1);
        const uint32_t baseA = sA + (uint32_t)st * STAGE_B;
        const uint32_t baseB = sB + (uint32_t)st * STAGE_B;
#pragma unroll
        for (int kk = 0; kk < 2; kk++) {
            uint32_t af[4][4], bf_[2][4];
#pragma unroll
            for (int mt = 0; mt < 4; mt++) {
                const uint32_t ad = baseA +
                    (uint32_t)((wm * 64 + mt * 16 + a_ro) * LDA + kk * 16 + a_co) * 2;
                LDMX4(af[mt], ad);
            }
#pragma unroll
            for (int nt = 0; nt < 2; nt++) {
                const uint32_t bd = baseB +
                    (uint32_t)((wn * 32 + nt * 16 + b_ro) * LDA + kk * 16 + b_co) * 2;
                LDMX4(bf_[nt], bd);
            }
#pragma unroll
            for (int mt = 0; mt < 4; mt++)
#pragma unroll
                for (int nb = 0; nb < 4; nb++)
                    MMA16816(acc[mt][nb], af[mt],
                             bf_[nb >> 1][(nb & 1) * 2], bf_[nb >> 1][(nb & 1) * 2 + 1]);
        }
    }

    const int er = lid >> 2, ec = (lid & 3) * 2;
#pragma unroll
    for (int mt = 0; mt < 4; mt++) {
#pragma unroll
        for (int nb = 0; nb < 4; nb++) {
            const int row = m0 + wm * 64 + mt * 16 + er;
            const int col = n0 + wn * 32 + nb * 8 + ec;
#pragma unroll
            for (int half = 0; half < 2; half++) {
                const size_t o = (size_t)(row + half * 8) * ldc + col;
                float v0 = acc[mt][nb][half * 2 + 0];
                float v1 = acc[mt][nb][half * 2 + 1];
                if (EPI == 1) {
                    float2 fv; fv.x = v0; fv.y = v1;
                    *(float2*)&outF[o] = fv;
                } else if (EPI == 2) {
                    const __nv_bfloat16 h0 = __float2bfloat16(v0);
                    const __nv_bfloat16 h1 = __float2bfloat16(v1);
                    __nv_bfloat162 hv; hv.x = h0; hv.y = h1;
                    *(__nv_bfloat162*)&outH[o] = hv;
                    __nv_bfloat162 lv;
                    lv.x = __float2bfloat16(v0 - __bfloat162float(h0));
                    lv.y = __float2bfloat16(v1 - __bfloat162float(h1));
                    *(__nv_bfloat162*)&outL[o] = lv;
                } else {  // EPI == 3
                    float2 fv; fv.x = v0 + bias[col]; fv.y = v1 + bias[col + 1];
                    *(float2*)&outF[o] = fv;
                }
            }
        }
    }
}

// ---------------------------------------------------------------------------
// Symmetric masked GEMM (GEMM-3): G = At @ At^T (symmetric). Compute only
// upper-triangular 128x128 tile pairs (bi <= bj); each tile emits BOTH
// Prm blocks:  Prm[m][n] = G[m][n] * S[n][m]
//   tile B (rows n0+*, cols m0+*): Prm[n0+c][m0+r] = g(r,c)*S[(m0+r)][n0+c]
//       (aligned S read; smem-staged transpose; coalesced 128B writes)
//   tile A (rows m0+*, cols n0+*): Prm[m0+r][n0+c] = g(r,c)*S[(n0+c)][m0+r]
//       (S^T tile staged through smem; fragment-pattern store)
// Diagonal blocks (bi==bj): tile B alone covers the block; skip tile A.
// ---------------------------------------------------------------------------
#define SYM_LD 136   // smem row pitch (bf16) for epilogue staging

__global__ __launch_bounds__(256, 1)
void tensor_gemm_sym(const __nv_bfloat16* __restrict__ At,
                     const float* __restrict__ Smask,
                     __nv_bfloat16* __restrict__ Prm)
{
    extern __shared__ char dsm[];
    const uint32_t sA = smem_u32(dsm);
    const uint32_t sB = sA + STAGES * STAGE_B;

    const int tid = threadIdx.x;
    const int lid = tid & 31, wid = tid >> 5;
    const int wm = wid >> 2, wn = wid & 3;

    // linear block index -> upper-triangular pair (bi <= bj), 32x32 tile grid
    int bi = 0, rem = blockIdx.x;
    while (rem >= 32 - bi) { rem -= (32 - bi); bi++; }
    const int bj = bi + rem;
    const int m0 = bi * 128, n0 = bj * 128;

    const int r = tid >> 1, h = tid & 1;
    const int lr = lid & 7, grp = lid >> 3;
    const int a_ro = (grp & 1) * 8 + lr, a_co = (grp >> 1) * 8;
    const int b_ro = (grp >> 1) * 8 + lr, b_co = (grp & 1) * 8;

    float acc[4][4][4];
#pragma unroll
    for (int i = 0; i < 4; i++)
#pragma unroll
        for (int j = 0; j < 4; j++)
#pragma unroll
            for (int q = 0; q < 4; q++) acc[i][j][q] = 0.0f;

    const int T2 = 2 * (NN_ / 64);

    auto issue = [&](int t) {
        if (t < T2) {
            const int st = t & (STAGES - 1);
            const size_t koff = (size_t)t * 32 + (size_t)h * 16;
            const __nv_bfloat16* ga = At + (size_t)(m0 + r) * NN_ + koff;
            const __nv_bfloat16* gb = At + (size_t)(n0 + r) * NN_ + koff;
            const uint32_t da = sA + st * STAGE_B + (uint32_t)(r * LDA + h * 16) * 2;
            const uint32_t db = sB + st * STAGE_B + (uint32_t)(r * LDA + h * 16) * 2;
            cp16(da, ga); cp16(da + 16, ga + 8);
            cp16(db, gb); cp16(db + 16, gb + 8);
        }
        CP_COMMIT();
    };

    issue(0); issue(1); issue(2);

    for (int kt = 0; kt < T2; kt++) {
        CP_WAIT2();
        __syncthreads();
        issue(kt + 3);

        const int st = kt & (STAGES - 1);
        const uint32_t baseA = sA + (uint32_t)st * STAGE_B;
        const uint32_t baseB = sB + (uint32_t)st * STAGE_B;
#pragma unroll
        for (int kk = 0; kk < 2; kk++) {
            uint32_t af[4][4], bf_[2][4];
#pragma unroll
            for (int mt = 0; mt < 4; mt++) {
                const uint32_t ad = baseA +
                    (uint32_t)((wm * 64 + mt * 16 + a_ro) * LDA + kk * 16 + a_co) * 2;
                LDMX4(af[mt], ad);
            }
#pragma unroll
            for (int nt = 0; nt < 2; nt++) {
                const uint32_t bd = baseB +
                    (uint32_t)((wn * 32 + nt * 16 + b_ro) * LDA + kk * 16 + b_co) * 2;
                LDMX4(bf_[nt], bd);
            }
#pragma unroll
            for (int mt = 0; mt < 4; mt++)
#pragma unroll
                for (int nb = 0; nb < 4; nb++)
                    MMA16816(acc[mt][nb], af[mt],
                             bf_[nb >> 1][(nb & 1) * 2], bf_[nb >> 1][(nb & 1) * 2 + 1]);
        }
    }

    // ---- epilogue: reuse dsm for staging (all cp.async data consumed) ----
    __syncthreads();
    __nv_bfloat16* smB = (__nv_bfloat16*)dsm;                      // [128][SYM_LD]
    __nv_bfloat16* smS = (__nv_bfloat16*)(dsm + 128 * SYM_LD * 2); // [128][SYM_LD]

    const int er = lid >> 2, ec = (lid & 3) * 2;

    // stage 1: masked (aligned S) values -> smB transposed: smB[c][r]
#pragma unroll
    for (int mt = 0; mt < 4; mt++)
#pragma unroll
        for (int nb = 0; nb < 4; nb++) {
            const int rl = wm * 64 + mt * 16 + er;
            const int cl = wn * 32 + nb * 8 + ec;
#pragma unroll
            for (int half = 0; half < 2; half++) {
                const int rr = rl + half * 8;
                const float2 sv = *(const float2*)&Smask[(size_t)(m0 + rr) * NN_ + n0 + cl];
                smB[(cl + 0) * SYM_LD + rr] =
                    __float2bfloat16(acc[mt][nb][half * 2 + 0] * sv.x);
                smB[(cl + 1) * SYM_LD + rr] =
                    __float2bfloat16(acc[mt][nb][half * 2 + 1] * sv.y);
            }
        }
    __syncthreads();

    // tile B write (coalesced): Prm[(n0+cc)][m0 + 0..127]
    {
        const int cc = tid >> 1, part = tid & 1;
        const uint4* src = (const uint4*)&smB[cc * SYM_LD + part * 64];
        uint4* dst = (uint4*)&Prm[(size_t)(n0 + cc) * NN_ + m0 + part * 64];
#pragma unroll
        for (int i = 0; i < 8; i++) dst[i] = src[i];
    }

    if (bi != bj) {
        __syncthreads();
        // load S^T tile: smS[c][r] = S[(n0+c)][m0+r]  (coalesced by c-rows)
        {
            const int cc = tid >> 1, part = tid & 1;
            const float* src = &Smask[(size_t)(n0 + cc) * NN_ + m0 + part * 64];
            __nv_bfloat16* dst = &smS[cc * SYM_LD + part * 64];
#pragma unroll 8
            for (int i = 0; i < 64; i++) dst[i] = __float2bfloat16(src[i]);
        }
        __syncthreads();
        // tile A write (fragment pattern): Prm[(m0+r)][n0+c] = g * S[n0+c][m0+r]
#pragma unroll
        for (int mt = 0; mt < 4; mt++)
#pragma unroll
            for (int nb = 0; nb < 4; nb++) {
                const int rl = wm * 64 + mt * 16 + er;
                const int cl = wn * 32 + nb * 8 + ec;
#pragma unroll
                for (int half = 0; half < 2; half++) {
                    const int rr = rl + half * 8;
                    __nv_bfloat162 hv;
                    hv.x = __float2bfloat16(acc[mt][nb][half * 2 + 0] *
                            __bfloat162float(smS[(cl + 0) * SYM_LD + rr]));
                    hv.y = __float2bfloat16(acc[mt][nb][half * 2 + 1] *
                            __bfloat162float(smS[(cl + 1) * SYM_LD + rr]));
                    *(__nv_bfloat162*)&Prm[(size_t)(m0 + rr) * NN_ + n0 + cl] = hv;
                }
            }
    }
}

// ---------------------------------------------------------------------------
// Helper passes
// ---------------------------------------------------------------------------
template<bool SPLIT>
__global__ __launch_bounds__(256)
void transpose_cvt(const float* __restrict__ in, __nv_bfloat16* __restrict__ oh,
                   __nv_bfloat16* __restrict__ ol, int R, int C)
{
    __shared__ float t[32][33];
    const int rb = blockIdx.y * 32, cb = blockIdx.x * 32;
    const int tx = threadIdx.x, ty = threadIdx.y;
#pragma unroll
    for (int rr = 0; rr < 32; rr += 8)
        t[ty + rr][tx] = in[(size_t)(rb + ty + rr) * C + (cb + tx)];
    __syncthreads();
#pragma unroll
    for (int rr = 0; rr < 32; rr += 8) {
        const float v = t[tx][ty + rr];
        const size_t o = (size_t)(cb + ty + rr) * R + (rb + tx);
        const __nv_bfloat16 hh = __float2bfloat16(v);
        oh[o] = hh;
        if (SPLIT) ol[o] = __float2bfloat16(v - __bfloat162float(hh));
    }
}

__global__ __launch_bounds__(256)
void split_cvt(const float* __restrict__ in, __nv_bfloat16* __restrict__ oh,
               __nv_bfloat16* __restrict__ ol, size_t n)
{
    const size_t i = (size_t)blockIdx.x * 256 + threadIdx.x;
    if (i < n) {
        const float v = in[i];
        const __nv_bfloat16 hh = __float2bfloat16(v);
        oh[i] = hh;
        ol[i] = __float2bfloat16(v - __bfloat162float(hh));
    }
}

// c2[n] = sum_i lb[i] * W[i][n]
__global__ __launch_bounds__(256)
void bias_w_kernel(const float* __restrict__ lb, const float* __restrict__ w,
                   float* __restrict__ c2)
{
    const int n = blockIdx.x * 256 + threadIdx.x;
    float s = 0.0f;
#pragma unroll 8
    for (int i = 0; i < INF; i++) s = fmaf(lb[i], w[(size_t)i * OUTF + n], s);
    c2[n] = s;
}

// out[k][j] = wf[j][k] * PW[j][k] / nc[k]^2
__global__ __launch_bounds__(256)
void finalize_kernel(const float* __restrict__ wf, const float* __restrict__ PW,
                     const float* __restrict__ nc, float* __restrict__ out)
{
    __shared__ float t[32][33];
    const int kb = blockIdx.x * 32;
    const int jb = blockIdx.y * 32;
    const int tx = threadIdx.x, ty = threadIdx.y;
#pragma unroll
    for (int rr = 0; rr < 32; rr += 8) {
        const size_t idx = (size_t)(jb + ty + rr) * NN_ + (kb + tx);
        t[ty + rr][tx] = wf[idx] * PW[idx];
    }
    __syncthreads();
#pragma unroll
    for (int rr = 0; rr < 32; rr += 8) {
        const int k = kb + ty + rr;
        const float n = nc[k];
        const float inv = 1.0f / (n * n);
        out[(size_t)k * NN_ + (jb + tx)] = t[tx][ty + rr] * inv;
    }
}

// ---------------------------------------------------------------------------
extern "C" void kernel_launch(void* const* d_in, const int* in_sizes, int n_in,
                              void* d_out, int out_size)
{
    const float* nf  = (const float*)d_in[0];  // (4096, 512)
    const float* adj = (const float*)d_in[1];  // (4096, 4096)
    const float* nc  = (const float*)d_in[3];  // (4096, 1)
    const float* S   = (const float*)d_in[4];  // mask_hadamard == S (4096, 4096)
    const float* lw  = (const float*)d_in[5];  // (1024, 512)
    const float* lb  = (const float*)d_in[6];  // (1024,)
    const float* w   = (const float*)d_in[7];  // (1024, 4096)
    float* out = (float*)d_out;

    float *wf, *PW, *c2;
    __nv_bfloat16 *Wth, *Wtl, *lwTh, *lwTl, *NFh, *NFl, *C1th, *C1tl, *At, *wfTh, *wfTl, *Prm;
    cudaGetSymbolAddress((void**)&Wth,  g_Wth);
    cudaGetSymbolAddress((void**)&Wtl,  g_Wtl);
    cudaGetSymbolAddress((void**)&lwTh, g_lwTh);
    cudaGetSymbolAddress((void**)&lwTl, g_lwTl);
    cudaGetSymbolAddress((void**)&NFh,  g_NFh);
    cudaGetSymbolAddress((void**)&NFl,  g_NFl);
    cudaGetSymbolAddress((void**)&C1th, g_C1th);
    cudaGetSymbolAddress((void**)&C1tl, g_C1tl);
    cudaGetSymbolAddress((void**)&c2,   g_c2);
    cudaGetSymbolAddress((void**)&At,   g_At);
    cudaGetSymbolAddress((void**)&wf,   g_wf);
    cudaGetSymbolAddress((void**)&wfTh, g_wfTh);
    cudaGetSymbolAddress((void**)&wfTl, g_wfTl);
    cudaGetSymbolAddress((void**)&Prm,  g_Prm);
    cudaGetSymbolAddress((void**)&PW,   g_PW);

    cudaFuncSetAttribute(tensor_gemm<1>, cudaFuncAttributeMaxDynamicSharedMemorySize, DSM_BYTES);
    cudaFuncSetAttribute(tensor_gemm<2>, cudaFuncAttributeMaxDynamicSharedMemorySize, DSM_BYTES);
    cudaFuncSetAttribute(tensor_gemm<3>, cudaFuncAttributeMaxDynamicSharedMemorySize, DSM_BYTES);
    cudaFuncSetAttribute(tensor_gemm_sym, cudaFuncAttributeMaxDynamicSharedMemorySize, DSM_BYTES);

    // --- operand prep ---
    transpose_cvt<true ><<<dim3(OUTF/32, INF/32), dim3(32, 8)>>>(w, Wth, Wtl, INF, OUTF);
    transpose_cvt<true ><<<dim3(FRAW/32, INF/32), dim3(32, 8)>>>(lw, lwTh, lwTl, INF, FRAW);
    split_cvt<<<(unsigned)(((size_t)NN_*FRAW + 255)/256), 256>>>(nf, NFh, NFl, (size_t)NN_*FRAW);
    transpose_cvt<false><<<dim3(NN_/32, NN_/32), dim3(32, 8)>>>(adj, At, nullptr, NN_, NN_);
    bias_w_kernel<<<OUTF/256, 256>>>(lb, w, c2);

    // --- C1^T = W^T @ lw  (4096 x 512), 3-term split, bf16 hi/lo out ---
    tensor_gemm<2><<<dim3(FRAW/128, OUTF/128), 256, DSM_BYTES>>>(
        Wth, lwTh, INF/64,  Wth, lwTl, INF/64,  Wtl, lwTh, INF/64,
        nullptr, C1th, C1tl, nullptr, FRAW);

    // --- wf = NF @ C1 + c2   (K = 512, 3-term split, fp32 out + bias) ---
    tensor_gemm<3><<<dim3(OUTF/128, NN_/128), 256, DSM_BYTES>>>(
        NFh, C1th, FRAW/64,  NFh, C1tl, FRAW/64,  NFl, C1th, FRAW/64,
        wf, nullptr, nullptr, c2, OUTF);

    // --- wf^T hi/lo split for GEMM-4's B operand ---
    transpose_cvt<true><<<dim3(OUTF/32, NN_/32), dim3(32, 8)>>>(wf, wfTh, wfTl, NN_, OUTF);

    // --- GEMM-3 (bf16, exact, symmetric): Prm = (A^T A) .* S^T, both halves
    //     from 528 upper-triangular tiles ---
    tensor_gemm_sym<<<528, 256, DSM_BYTES>>>(At, S, Prm);

    // --- GEMM-4 (bf16, wf split): PW = P@wfh + P@wfl ---
    tensor_gemm<1><<<dim3(OUTF/128, NN_/128), 256, DSM_BYTES>>>(
        Prm, wfTh, NN_/64,  Prm, wfTl, NN_/64,  nullptr, nullptr, 0,
        PW, nullptr, nullptr, nullptr, OUTF);

    // --- out[k][j] = wf[j][k]*PW[j][k]/nc[k]^2 ---
    finalize_kernel<<<dim3(NN_/32, NN_/32), dim3(32, 8)>>>(wf, PW, nc, out);
}